// round 12
// baseline (speedup 1.0000x reference)
#include <cuda_runtime.h>
#include <cuda_bf16.h>
#include <math_constants.h>

#define NN 100000
#define EE 1600000
#define DD 192
#define HH 4
#define DHH 48
#define D3 576
#define DFF 384
#define NB 98

typedef __nv_bfloat16 bf16;

// ---------------- scratch ----------------
__device__ int g_is_int32;
__device__ int g_prefix[NN];
__device__ int g_bsum[NB];
__device__ int g_boff[NB];
__device__ int g_T;
__device__ int g_order[NN];
__device__ int g_inv[NN];
__device__ int g_rowstart[NN + 1];
__device__ bf16 g_hnb[(size_t)NN * DD];
__device__ bf16 g_qb[(size_t)NN * DD];
__device__ bf16 g_kb[(size_t)NN * DD];
__device__ bf16 g_vb[(size_t)NN * DD];
__device__ bf16 g_aggb[(size_t)NN * DD];
__device__ float g_proj[(size_t)NN * DD];
__device__ float g_t1[(size_t)NN * DD];
__device__ bf16 g_hn2b[(size_t)NN * DD];
__device__ bf16 g_mlp1b[(size_t)NN * DFF];
__device__ bf16 g_wqkvT[(size_t)D3 * DD];
__device__ bf16 g_woutT[(size_t)DD * DD];
__device__ bf16 g_w1T[(size_t)DFF * DD];
__device__ bf16 g_w2T[(size_t)DD * DFF];

__device__ __forceinline__ int read_mask(const void* mask, int i) {
    if (g_is_int32) return ((const int*)mask)[i] != 0;
    return ((const unsigned char*)mask)[i] != 0;
}

// ---------------- fused weight transpose + flag init ----------------
__global__ void wtrans_all_kernel(const float* __restrict__ Wqkv, const float* __restrict__ Wout,
                                  const float* __restrict__ W1, const float* __restrict__ W2) {
    const int S0 = DD * D3;
    const int S1 = S0 + DD * DD;
    const int S2 = S1 + DD * DFF;
    const int S3 = S2 + DFF * DD;
    int idx = blockIdx.x * blockDim.x + threadIdx.x;
    if (idx == 0) g_is_int32 = 1;
    if (idx >= S3) return;
    const float* W; bf16* Wt; int K, Nw, local;
    if (idx < S0) { W = Wqkv; Wt = g_wqkvT; K = DD; Nw = D3; local = idx; }
    else if (idx < S1) { W = Wout; Wt = g_woutT; K = DD; Nw = DD; local = idx - S0; }
    else if (idx < S2) { W = W1; Wt = g_w1T; K = DD; Nw = DFF; local = idx - S1; }
    else { W = W2; Wt = g_w2T; K = DFF; Nw = DD; local = idx - S2; }
    int n = local / K;
    int k = local - n * K;
    Wt[local] = __float2bfloat16_rn(W[(size_t)k * Nw + n]);
}

__global__ void detect_mask_kernel(const unsigned* __restrict__ m) {
    int i = blockIdx.x * blockDim.x + threadIdx.x;
    if (i >= NN / 4) return;
    if (m[i] > 1u) atomicExch(&g_is_int32, 0);
}

// ---------------- multi-block scan ----------------
__global__ void blockscan_kernel(const void* __restrict__ mask) {
    int tid = threadIdx.x;
    int i = blockIdx.x * 1024 + tid;
    int v = (i < NN) ? read_mask(mask, i) : 0;
    int lane = tid & 31, wid = tid >> 5;
    int s = v;
#pragma unroll
    for (int off = 1; off < 32; off <<= 1) {
        int t = __shfl_up_sync(0xffffffffu, s, off);
        if (lane >= off) s += t;
    }
    __shared__ int wsum[32];
    if (lane == 31) wsum[wid] = s;
    __syncthreads();
    if (wid == 0) {
        int ws = wsum[lane];
#pragma unroll
        for (int off = 1; off < 32; off <<= 1) {
            int t = __shfl_up_sync(0xffffffffu, ws, off);
            if (lane >= off) ws += t;
        }
        wsum[lane] = ws;
    }
    __syncthreads();
    int incl = s + (wid > 0 ? wsum[wid - 1] : 0);
    if (i < NN) g_prefix[i] = incl;
    if (tid == 1023) g_bsum[blockIdx.x] = incl;
}

__global__ void scan_sums_kernel() {
    int tid = threadIdx.x;
    int v = (tid < NB) ? g_bsum[tid] : 0;
    int lane = tid & 31, wid = tid >> 5;
    int s = v;
#pragma unroll
    for (int off = 1; off < 32; off <<= 1) {
        int t = __shfl_up_sync(0xffffffffu, s, off);
        if (lane >= off) s += t;
    }
    __shared__ int wsum[4];
    if (lane == 31) wsum[wid] = s;
    __syncthreads();
    int add = 0;
    for (int w = 0; w < wid; w++) add += wsum[w];
    int incl = s + add;
    if (tid < NB) g_boff[tid] = incl - v;
    if (tid == NB - 1) g_T = incl;
}

__global__ void ranks_kernel(const void* __restrict__ mask) {
    int i = blockIdx.x * blockDim.x + threadIdx.x;
    if (i >= NN) return;
    int inc = g_prefix[i] + g_boff[i >> 10];
    int T = g_T;
    int r = read_mask(mask, i) ? (inc - 1) : (T + i - inc);
    g_order[i] = r;
    g_inv[r] = i;
}

// ---------------- LN1 with row gather, bf16 output ----------------
__global__ void ln_kernel(const float* __restrict__ in, const float* __restrict__ g,
                          const float* __restrict__ b) {
    int row = blockIdx.x * 8 + (threadIdx.x >> 5);
    if (row >= NN) return;
    int lane = threadIdx.x & 31;
    const float* p = in + (size_t)g_order[row] * DD;
    float vals[6];
    float s = 0.f;
#pragma unroll
    for (int j = 0; j < 6; j++) { vals[j] = p[lane + j * 32]; s += vals[j]; }
#pragma unroll
    for (int off = 16; off > 0; off >>= 1) s += __shfl_xor_sync(0xffffffffu, s, off);
    float mu = s * (1.f / DD);
    float vs = 0.f;
#pragma unroll
    for (int j = 0; j < 6; j++) { float d = vals[j] - mu; vs += d * d; }
#pragma unroll
    for (int off = 16; off > 0; off >>= 1) vs += __shfl_xor_sync(0xffffffffu, vs, off);
    float r = rsqrtf(vs * (1.f / DD) + 1e-5f);
    bf16* o = g_hnb + (size_t)row * DD;
#pragma unroll
    for (int j = 0; j < 6; j++) {
        int c = lane + j * 32;
        o[c] = __float2bfloat16_rn((vals[j] - mu) * r * g[c] + b[c]);
    }
}

// ---------------- fused residual+unpermute+LN2 ----------------
__global__ void resln_kernel(const float* __restrict__ x, const float* __restrict__ g,
                             const float* __restrict__ b) {
    int row = blockIdx.x * 8 + (threadIdx.x >> 5);
    if (row >= NN) return;
    int lane = threadIdx.x & 31;
    const float* xp = x + (size_t)row * DD;
    const float* pp = g_proj + (size_t)g_inv[row] * DD;
    float* t1p = g_t1 + (size_t)row * DD;
    float vals[6];
    float s = 0.f;
#pragma unroll
    for (int j = 0; j < 6; j++) {
        int c = lane + j * 32;
        vals[j] = xp[c] + pp[c];
        t1p[c] = vals[j];
        s += vals[j];
    }
#pragma unroll
    for (int off = 16; off > 0; off >>= 1) s += __shfl_xor_sync(0xffffffffu, s, off);
    float mu = s * (1.f / DD);
    float vs = 0.f;
#pragma unroll
    for (int j = 0; j < 6; j++) { float d = vals[j] - mu; vs += d * d; }
#pragma unroll
    for (int off = 16; off > 0; off >>= 1) vs += __shfl_xor_sync(0xffffffffu, vs, off);
    float r = rsqrtf(vs * (1.f / DD) + 1e-5f);
    bf16* o = g_hn2b + (size_t)row * DD;
#pragma unroll
    for (int j = 0; j < 6; j++) {
        int c = lane + j * 32;
        o[c] = __float2bfloat16_rn((vals[j] - mu) * r * g[c] + b[c]);
    }
}

// ---------------- CSR row offsets ----------------
__global__ void rowstart_kernel(const int* __restrict__ dst) {
    int e = blockIdx.x * blockDim.x + threadIdx.x;
    if (e >= EE) return;
    int cur = dst[e];
    int prev = (e == 0) ? -1 : dst[e - 1];
    for (int n = prev + 1; n <= cur; n++) g_rowstart[n] = e;
    if (e == EE - 1) {
        for (int n = cur + 1; n <= NN; n++) g_rowstart[n] = EE;
    }
}

// ---------------- graph attention: 2-edge loop, raw-word v storage ----------------
__device__ __forceinline__ float dot6(float2 q0, float2 q1, float2 q2,
                                      unsigned k0, unsigned k1, unsigned k2) {
    float2 a = __bfloat1622float2(*(__nv_bfloat162*)&k0);
    float2 b = __bfloat1622float2(*(__nv_bfloat162*)&k1);
    float2 c = __bfloat1622float2(*(__nv_bfloat162*)&k2);
    return q0.x * a.x + q0.y * a.y + q1.x * b.x + q1.y * b.y + q2.x * c.x + q2.y * c.y;
}

__global__ void attn_kernel(const int* __restrict__ src) {
    int warp = (blockIdx.x * blockDim.x + threadIdx.x) >> 5;
    if (warp >= NN) return;
    int lane = threadIdx.x & 31;
    int off = (lane >> 3) * DHH + (lane & 7) * 6;
    const unsigned* qp = (const unsigned*)(g_qb + (size_t)warp * DD + off);
    unsigned qw0 = qp[0], qw1 = qp[1], qw2 = qp[2];
    float2 q0 = __bfloat1622float2(*(__nv_bfloat162*)&qw0);
    float2 q1 = __bfloat1622float2(*(__nv_bfloat162*)&qw1);
    float2 q2 = __bfloat1622float2(*(__nv_bfloat162*)&qw2);

    int s0 = g_rowstart[warp];
    int s1 = g_rowstart[warp + 1];
    const float coef = 0.14433756729740643f;
    float l = 0.f;
    float acc[6] = {0.f, 0.f, 0.f, 0.f, 0.f, 0.f};

    int e = s0;
    for (; e + 1 < s1; e += 2) {
        int sn0 = src[e], sn1 = src[e + 1];
        const unsigned* kp0 = (const unsigned*)(g_kb + (size_t)sn0 * DD + off);
        const unsigned* vp0 = (const unsigned*)(g_vb + (size_t)sn0 * DD + off);
        const unsigned* kp1 = (const unsigned*)(g_kb + (size_t)sn1 * DD + off);
        const unsigned* vp1 = (const unsigned*)(g_vb + (size_t)sn1 * DD + off);
        unsigned vw0[3], vw1[3];
        float p0 = dot6(q0, q1, q2, kp0[0], kp0[1], kp0[2]);
        vw0[0] = vp0[0]; vw0[1] = vp0[1]; vw0[2] = vp0[2];
        float p1 = dot6(q0, q1, q2, kp1[0], kp1[1], kp1[2]);
        vw1[0] = vp1[0]; vw1[1] = vp1[1]; vw1[2] = vp1[2];
#pragma unroll
        for (int d = 1; d < 8; d <<= 1) {
            p0 += __shfl_xor_sync(0xffffffffu, p0, d);
            p1 += __shfl_xor_sync(0xffffffffu, p1, d);
        }
        float e0 = __expf(p0 * coef);
        float e1 = __expf(p1 * coef);
        l += e0 + e1;
#pragma unroll
        for (int j = 0; j < 3; j++) {
            float2 v0 = __bfloat1622float2(*(__nv_bfloat162*)&vw0[j]);
            float2 v1 = __bfloat1622float2(*(__nv_bfloat162*)&vw1[j]);
            acc[2 * j] += e0 * v0.x + e1 * v1.x;
            acc[2 * j + 1] += e0 * v0.y + e1 * v1.y;
        }
    }
    if (e < s1) {
        int sn = src[e];
        const unsigned* kp = (const unsigned*)(g_kb + (size_t)sn * DD + off);
        const unsigned* vp = (const unsigned*)(g_vb + (size_t)sn * DD + off);
        unsigned vw0 = vp[0], vw1 = vp[1], vw2 = vp[2];
        float p = dot6(q0, q1, q2, kp[0], kp[1], kp[2]);
#pragma unroll
        for (int d = 1; d < 8; d <<= 1) p += __shfl_xor_sync(0xffffffffu, p, d);
        float es = __expf(p * coef);
        l += es;
        float2 v0 = __bfloat1622float2(*(__nv_bfloat162*)&vw0);
        float2 v1 = __bfloat1622float2(*(__nv_bfloat162*)&vw1);
        float2 v2 = __bfloat1622float2(*(__nv_bfloat162*)&vw2);
        acc[0] += es * v0.x; acc[1] += es * v0.y;
        acc[2] += es * v1.x; acc[3] += es * v1.y;
        acc[4] += es * v2.x; acc[5] += es * v2.y;
    }
    float invl = (s1 > s0) ? (1.f / l) : 0.f;
    __nv_bfloat162* op = (__nv_bfloat162*)(g_aggb + (size_t)warp * DD + off);
#pragma unroll
    for (int j = 0; j < 3; j++)
        op[j] = __floats2bfloat162_rn(acc[2 * j] * invl, acc[2 * j + 1] * invl);
}

// ---------------- bf16 tensor-core GEMM: m16n8k16, 3-stage cp.async pipeline ----------------
#define BM 128
#define BN 64
#define BK 32
#define AKS 40
#define BKS 40
#define STAGES 3

__device__ __forceinline__ void mma_bf16(float& c0, float& c1, float& c2, float& c3,
                                         unsigned a0, unsigned a1, unsigned a2, unsigned a3,
                                         unsigned b0, unsigned b1) {
    asm volatile(
        "mma.sync.aligned.m16n8k16.row.col.f32.bf16.bf16.f32 "
        "{%0,%1,%2,%3}, {%4,%5,%6,%7}, {%8,%9}, {%0,%1,%2,%3};"
        : "+f"(c0), "+f"(c1), "+f"(c2), "+f"(c3)
        : "r"(a0), "r"(a1), "r"(a2), "r"(a3), "r"(b0), "r"(b1));
}

// mode: 0 proj fp32, 1 gelu->bf16 mlp1, 2 residual->out fp32, 3 qkv scatter (all bf16)
__global__ void __launch_bounds__(256) gemm_kernel(
        const bf16* __restrict__ A, const bf16* __restrict__ Bt,
        const float* __restrict__ bias, float* __restrict__ out,
        const float* __restrict__ res, int M, int K, int Nc, int mode) {
    __shared__ bf16 As[STAGES][BM][AKS];
    __shared__ bf16 Bs[STAGES][BN][BKS];
    int tid = threadIdx.x;
    int lane = tid & 31;
    int wid = tid >> 5;
    int warp_m = wid & 3;
    int warp_n = wid >> 2;
    int m0 = blockIdx.y * BM;
    int n0 = blockIdx.x * BN;
    int gid = lane >> 2;
    int tig = lane & 3;

    int cp_row = tid >> 2;
    int cp_c = (tid & 3) * 8;

    float acc[2][4][4];
#pragma unroll
    for (int mt = 0; mt < 2; mt++)
#pragma unroll
        for (int nt = 0; nt < 4; nt++)
#pragma unroll
            for (int j = 0; j < 4; j++) acc[mt][nt][j] = 0.f;

    int niter = K / BK;

#define LOAD_STAGE(it, buf)                                                            \
    {                                                                                  \
        int k0s = (it) * BK;                                                           \
        _Pragma("unroll")                                                              \
        for (int i = 0; i < 2; i++) {                                                  \
            int row = cp_row + i * 64;                                                 \
            const bf16* srcp = A + (size_t)(m0 + row) * K + k0s + cp_c;                \
            unsigned dstp = (unsigned)__cvta_generic_to_shared(&As[buf][row][cp_c]);   \
            int sz = (m0 + row < M) ? 16 : 0;                                          \
            asm volatile("cp.async.cg.shared.global [%0], [%1], 16, %2;\n"             \
                         :: "r"(dstp), "l"(srcp), "r"(sz));                            \
        }                                                                              \
        {                                                                              \
            const bf16* srcp = Bt + (size_t)(n0 + cp_row) * K + k0s + cp_c;            \
            unsigned dstp = (unsigned)__cvta_generic_to_shared(&Bs[buf][cp_row][cp_c]); \
            asm volatile("cp.async.cg.shared.global [%0], [%1], 16;\n"                 \
                         :: "r"(dstp), "l"(srcp));                                     \
        }                                                                              \
        asm volatile("cp.async.commit_group;\n");                                      \
    }

    // prefetch 2 stages ahead
    LOAD_STAGE(0, 0);
    LOAD_STAGE(1, 1);

    for (int it = 0; it < niter; it++) {
        int buf = it % STAGES;
        // ensure stage `it` is complete:
        // issued = min(it+2, niter); need completed >= it+1
        if (it + 2 <= niter) {
            asm volatile("cp.async.wait_group 1;\n" ::: "memory");
        } else {
            asm volatile("cp.async.wait_group 0;\n" ::: "memory");
        }
        __syncthreads();
        if (it + 2 < niter) LOAD_STAGE(it + 2, (it + 2) % STAGES);

#pragma unroll
        for (int kk = 0; kk < 2; kk++) {
            int w0 = kk * 8 + tig;
            unsigned a[2][4];
#pragma unroll
            for (int mt = 0; mt < 2; mt++) {
                int r = warp_m * 32 + mt * 16 + gid;
                const unsigned* r0 = (const unsigned*)&As[buf][r][0];
                const unsigned* r8 = (const unsigned*)&As[buf][r + 8][0];
                a[mt][0] = r0[w0];
                a[mt][1] = r8[w0];
                a[mt][2] = r0[w0 + 4];
                a[mt][3] = r8[w0 + 4];
            }
            unsigned b[4][2];
#pragma unroll
            for (int nt = 0; nt < 4; nt++) {
                int n = warp_n * 32 + nt * 8 + gid;
                const unsigned* rn = (const unsigned*)&Bs[buf][n][0];
                b[nt][0] = rn[w0];
                b[nt][1] = rn[w0 + 4];
            }
#pragma unroll
            for (int mt = 0; mt < 2; mt++)
#pragma unroll
                for (int nt = 0; nt < 4; nt++)
                    mma_bf16(acc[mt][nt][0], acc[mt][nt][1], acc[mt][nt][2], acc[mt][nt][3],
                             a[mt][0], a[mt][1], a[mt][2], a[mt][3],
                             b[nt][0], b[nt][1]);
        }
        __syncthreads();
    }

    // epilogue
#pragma unroll
    for (int mt = 0; mt < 2; mt++) {
#pragma unroll
        for (int nt = 0; nt < 4; nt++) {
#pragma unroll
            for (int half = 0; half < 2; half++) {
                int m = m0 + warp_m * 32 + mt * 16 + gid + half * 8;
                if (m >= M) continue;
#pragma unroll
                for (int j = 0; j < 2; j++) {
                    int n = n0 + warp_n * 32 + nt * 8 + 2 * tig + j;
                    float val = acc[mt][nt][half * 2 + j] + bias[n];
                    if (mode == 0) {
                        out[(size_t)m * Nc + n] = val;
                    } else if (mode == 1) {
                        g_mlp1b[(size_t)m * DFF + n] = __float2bfloat16_rn(val * normcdff(val));
                    } else if (mode == 2) {
                        out[(size_t)m * Nc + n] = val + res[(size_t)m * Nc + n];
                    } else {
                        int hh = n / 144;
                        int r = n - hh * 144;
                        int w = r / DHH;
                        int dd = r - w * DHH;
                        size_t o = (size_t)m * DD + hh * DHH + dd;
                        bf16 bv = __float2bfloat16_rn(val);
                        if (w == 0) g_qb[o] = bv;
                        else if (w == 1) g_kb[o] = bv;
                        else g_vb[o] = bv;
                    }
                }
            }
        }
    }
}

// ---------------- launch ----------------
static inline void* sym(const void* s) {
    void* p = nullptr;
    cudaGetSymbolAddress(&p, s);
    return p;
}

extern "C" void kernel_launch(void* const* d_in, const int* in_sizes, int n_in,
                              void* d_out, int out_size) {
    const float* x = (const float*)d_in[0];
    const void* mask = d_in[1];
    const int* src = (const int*)d_in[2];
    const int* dst = (const int*)d_in[3];
    const float* ln1_g = (const float*)d_in[4];
    const float* ln1_b = (const float*)d_in[5];
    const float* Wqkv = (const float*)d_in[6];
    const float* bqkv = (const float*)d_in[7];
    const float* Wout = (const float*)d_in[8];
    const float* bout = (const float*)d_in[9];
    const float* ln2_g = (const float*)d_in[10];
    const float* ln2_b = (const float*)d_in[11];
    const float* W1 = (const float*)d_in[12];
    const float* b1 = (const float*)d_in[13];
    const float* W2 = (const float*)d_in[14];
    const float* b2 = (const float*)d_in[15];
    float* out = (float*)d_out;

    bf16* hnb = (bf16*)sym(g_hnb);
    bf16* aggb = (bf16*)sym(g_aggb);
    float* proj = (float*)sym(g_proj);
    float* t1 = (float*)sym(g_t1);
    bf16* hn2b = (bf16*)sym(g_hn2b);
    bf16* mlp1b = (bf16*)sym(g_mlp1b);
    bf16* wqkvT = (bf16*)sym(g_wqkvT);
    bf16* woutT = (bf16*)sym(g_woutT);
    bf16* w1T = (bf16*)sym(g_w1T);
    bf16* w2T = (bf16*)sym(g_w2T);

    // 0. prep: weight transposes (sets mask flag), then detect
    {
        int total = DD * D3 + DD * DD + DD * DFF + DFF * DD;
        wtrans_all_kernel<<<(total + 255) / 256, 256>>>(Wqkv, Wout, W1, W2);
    }
    detect_mask_kernel<<<(NN / 4 + 255) / 256, 256>>>((const unsigned*)mask);

    // 1. permutation
    blockscan_kernel<<<NB, 1024>>>(mask);
    scan_sums_kernel<<<1, 128>>>();
    ranks_kernel<<<(NN + 255) / 256, 256>>>(mask);

    // 2. LN1 fused with gather -> bf16
    ln_kernel<<<(NN + 7) / 8, 256>>>(x, ln1_g, ln1_b);

    // 3. CSR offsets
    rowstart_kernel<<<(EE + 255) / 256, 256>>>(dst);

    // 4. QKV GEMM (scatter epilogue, all bf16)
    {
        dim3 grid(D3 / BN, (NN + BM - 1) / BM);
        gemm_kernel<<<grid, 256>>>(hnb, wqkvT, bqkv, nullptr, nullptr, NN, DD, D3, 3);
    }

    // 5. graph attention -> bf16 agg
    attn_kernel<<<(NN * 32 + 255) / 256, 256>>>(src);

    // 6. out-projection -> fp32 proj
    {
        dim3 grid(DD / BN, (NN + BM - 1) / BM);
        gemm_kernel<<<grid, 256>>>(aggb, woutT, bout, proj, nullptr, NN, DD, DD, 0);
    }

    // 7. fused residual + unpermute + LN2
    resln_kernel<<<(NN + 7) / 8, 256>>>(x, ln2_g, ln2_b);

    // 8. MLP up + GELU -> bf16 mlp1
    {
        dim3 grid(DFF / BN, (NN + BM - 1) / BM);
        gemm_kernel<<<grid, 256>>>(hn2b, w1T, b1, nullptr, nullptr, NN, DD, DFF, 1);
    }

    // 9. MLP down + residual -> out fp32
    {
        dim3 grid(DD / BN, (NN + BM - 1) / BM);
        gemm_kernel<<<grid, 256>>>(mlp1b, w2T, b2, out, t1, NN, DFF, DD, 2);
    }
}

// round 13
// speedup vs baseline: 1.0067x; 1.0067x over previous
#include <cuda_runtime.h>
#include <cuda_bf16.h>
#include <math_constants.h>

#define NN 100000
#define EE 1600000
#define DD 192
#define HH 4
#define DHH 48
#define D3 576
#define DFF 384
#define NB 98

typedef __nv_bfloat16 bf16;

// ---------------- scratch ----------------
__device__ int g_is_int32;
__device__ int g_prefix[NN];
__device__ int g_bsum[NB];
__device__ int g_boff[NB];
__device__ int g_T;
__device__ int g_inv[NN];
__device__ int g_rowstart[NN + 1];
__device__ bf16 g_hnb[(size_t)NN * DD];
__device__ bf16 g_qb[(size_t)NN * DD];
__device__ bf16 g_kb[(size_t)NN * DD];
__device__ bf16 g_vb[(size_t)NN * DD];
__device__ bf16 g_aggb[(size_t)NN * DD];
__device__ float g_proj[(size_t)NN * DD];
__device__ float g_t1[(size_t)NN * DD];
__device__ bf16 g_hn2b[(size_t)NN * DD];
__device__ bf16 g_mlp1b[(size_t)NN * DFF];
__device__ bf16 g_wqkvT[(size_t)D3 * DD];
__device__ bf16 g_woutT[(size_t)DD * DD];
__device__ bf16 g_w1T[(size_t)DFF * DD];
__device__ bf16 g_w2T[(size_t)DD * DFF];

__device__ __forceinline__ int read_mask(const void* mask, int i) {
    if (g_is_int32) return ((const int*)mask)[i] != 0;
    return ((const unsigned char*)mask)[i] != 0;
}

// ---------------- fused weight transpose + flag init ----------------
__global__ void wtrans_all_kernel(const float* __restrict__ Wqkv, const float* __restrict__ Wout,
                                  const float* __restrict__ W1, const float* __restrict__ W2) {
    const int S0 = DD * D3;
    const int S1 = S0 + DD * DD;
    const int S2 = S1 + DD * DFF;
    const int S3 = S2 + DFF * DD;
    int idx = blockIdx.x * blockDim.x + threadIdx.x;
    if (idx == 0) g_is_int32 = 1;
    if (idx >= S3) return;
    const float* W; bf16* Wt; int K, Nw, local;
    if (idx < S0) { W = Wqkv; Wt = g_wqkvT; K = DD; Nw = D3; local = idx; }
    else if (idx < S1) { W = Wout; Wt = g_woutT; K = DD; Nw = DD; local = idx - S0; }
    else if (idx < S2) { W = W1; Wt = g_w1T; K = DD; Nw = DFF; local = idx - S1; }
    else { W = W2; Wt = g_w2T; K = DFF; Nw = DD; local = idx - S2; }
    int n = local / K;
    int k = local - n * K;
    Wt[local] = __float2bfloat16_rn(W[(size_t)k * Nw + n]);
}

__global__ void detect_mask_kernel(const unsigned* __restrict__ m) {
    int i = blockIdx.x * blockDim.x + threadIdx.x;
    if (i >= NN / 4) return;
    if (m[i] > 1u) atomicExch(&g_is_int32, 0);
}

// ---------------- multi-block scan ----------------
__global__ void blockscan_kernel(const void* __restrict__ mask) {
    int tid = threadIdx.x;
    int i = blockIdx.x * 1024 + tid;
    int v = (i < NN) ? read_mask(mask, i) : 0;
    int lane = tid & 31, wid = tid >> 5;
    int s = v;
#pragma unroll
    for (int off = 1; off < 32; off <<= 1) {
        int t = __shfl_up_sync(0xffffffffu, s, off);
        if (lane >= off) s += t;
    }
    __shared__ int wsum[32];
    if (lane == 31) wsum[wid] = s;
    __syncthreads();
    if (wid == 0) {
        int ws = wsum[lane];
#pragma unroll
        for (int off = 1; off < 32; off <<= 1) {
            int t = __shfl_up_sync(0xffffffffu, ws, off);
            if (lane >= off) ws += t;
        }
        wsum[lane] = ws;
    }
    __syncthreads();
    int incl = s + (wid > 0 ? wsum[wid - 1] : 0);
    if (i < NN) g_prefix[i] = incl;
    if (tid == 1023) g_bsum[blockIdx.x] = incl;
}

__global__ void scan_sums_kernel() {
    int tid = threadIdx.x;
    int v = (tid < NB) ? g_bsum[tid] : 0;
    int lane = tid & 31, wid = tid >> 5;
    int s = v;
#pragma unroll
    for (int off = 1; off < 32; off <<= 1) {
        int t = __shfl_up_sync(0xffffffffu, s, off);
        if (lane >= off) s += t;
    }
    __shared__ int wsum[4];
    if (lane == 31) wsum[wid] = s;
    __syncthreads();
    int add = 0;
    for (int w = 0; w < wid; w++) add += wsum[w];
    int incl = s + add;
    if (tid < NB) g_boff[tid] = incl - v;
    if (tid == NB - 1) g_T = incl;
}

// ---------------- LN1 fused with rank computation + gather, bf16 output ----------------
// rank(row) = mask ? prefix-1 : T + row - prefix. hn[row] = LN(x[rank(row)]);
// also writes g_inv[rank(row)] = row (needed by resln).
__global__ void ln_rank_kernel(const float* __restrict__ in, const float* __restrict__ g,
                               const float* __restrict__ b, const void* __restrict__ mask) {
    int row = blockIdx.x * 8 + (threadIdx.x >> 5);
    if (row >= NN) return;
    int lane = threadIdx.x & 31;
    int inc = g_prefix[row] + g_boff[row >> 10];
    int r = read_mask(mask, row) ? (inc - 1) : (g_T + row - inc);
    if (lane == 0) g_inv[r] = row;
    const float* p = in + (size_t)r * DD;
    float vals[6];
    float s = 0.f;
#pragma unroll
    for (int j = 0; j < 6; j++) { vals[j] = p[lane + j * 32]; s += vals[j]; }
#pragma unroll
    for (int off = 16; off > 0; off >>= 1) s += __shfl_xor_sync(0xffffffffu, s, off);
    float mu = s * (1.f / DD);
    float vs = 0.f;
#pragma unroll
    for (int j = 0; j < 6; j++) { float d = vals[j] - mu; vs += d * d; }
#pragma unroll
    for (int off = 16; off > 0; off >>= 1) vs += __shfl_xor_sync(0xffffffffu, vs, off);
    float rr = rsqrtf(vs * (1.f / DD) + 1e-5f);
    bf16* o = g_hnb + (size_t)row * DD;
#pragma unroll
    for (int j = 0; j < 6; j++) {
        int c = lane + j * 32;
        o[c] = __float2bfloat16_rn((vals[j] - mu) * rr * g[c] + b[c]);
    }
}

// ---------------- fused residual+unpermute+LN2 ----------------
__global__ void resln_kernel(const float* __restrict__ x, const float* __restrict__ g,
                             const float* __restrict__ b) {
    int row = blockIdx.x * 8 + (threadIdx.x >> 5);
    if (row >= NN) return;
    int lane = threadIdx.x & 31;
    const float* xp = x + (size_t)row * DD;
    const float* pp = g_proj + (size_t)g_inv[row] * DD;
    float* t1p = g_t1 + (size_t)row * DD;
    float vals[6];
    float s = 0.f;
#pragma unroll
    for (int j = 0; j < 6; j++) {
        int c = lane + j * 32;
        vals[j] = xp[c] + pp[c];
        t1p[c] = vals[j];
        s += vals[j];
    }
#pragma unroll
    for (int off = 16; off > 0; off >>= 1) s += __shfl_xor_sync(0xffffffffu, s, off);
    float mu = s * (1.f / DD);
    float vs = 0.f;
#pragma unroll
    for (int j = 0; j < 6; j++) { float d = vals[j] - mu; vs += d * d; }
#pragma unroll
    for (int off = 16; off > 0; off >>= 1) vs += __shfl_xor_sync(0xffffffffu, vs, off);
    float r = rsqrtf(vs * (1.f / DD) + 1e-5f);
    bf16* o = g_hn2b + (size_t)row * DD;
#pragma unroll
    for (int j = 0; j < 6; j++) {
        int c = lane + j * 32;
        o[c] = __float2bfloat16_rn((vals[j] - mu) * r * g[c] + b[c]);
    }
}

// ---------------- CSR row offsets ----------------
__global__ void rowstart_kernel(const int* __restrict__ dst) {
    int e = blockIdx.x * blockDim.x + threadIdx.x;
    if (e >= EE) return;
    int cur = dst[e];
    int prev = (e == 0) ? -1 : dst[e - 1];
    for (int n = prev + 1; n <= cur; n++) g_rowstart[n] = e;
    if (e == EE - 1) {
        for (int n = cur + 1; n <= NN; n++) g_rowstart[n] = EE;
    }
}

// ---------------- graph attention: 2-edge loop, raw-word v storage ----------------
__device__ __forceinline__ float dot6(float2 q0, float2 q1, float2 q2,
                                      unsigned k0, unsigned k1, unsigned k2) {
    float2 a = __bfloat1622float2(*(__nv_bfloat162*)&k0);
    float2 b = __bfloat1622float2(*(__nv_bfloat162*)&k1);
    float2 c = __bfloat1622float2(*(__nv_bfloat162*)&k2);
    return q0.x * a.x + q0.y * a.y + q1.x * b.x + q1.y * b.y + q2.x * c.x + q2.y * c.y;
}

__global__ void attn_kernel(const int* __restrict__ src) {
    int warp = (blockIdx.x * blockDim.x + threadIdx.x) >> 5;
    if (warp >= NN) return;
    int lane = threadIdx.x & 31;
    int off = (lane >> 3) * DHH + (lane & 7) * 6;
    const unsigned* qp = (const unsigned*)(g_qb + (size_t)warp * DD + off);
    unsigned qw0 = qp[0], qw1 = qp[1], qw2 = qp[2];
    float2 q0 = __bfloat1622float2(*(__nv_bfloat162*)&qw0);
    float2 q1 = __bfloat1622float2(*(__nv_bfloat162*)&qw1);
    float2 q2 = __bfloat1622float2(*(__nv_bfloat162*)&qw2);

    int s0 = g_rowstart[warp];
    int s1 = g_rowstart[warp + 1];
    const float coef = 0.14433756729740643f;
    float l = 0.f;
    float acc[6] = {0.f, 0.f, 0.f, 0.f, 0.f, 0.f};

    int e = s0;
    for (; e + 1 < s1; e += 2) {
        int sn0 = src[e], sn1 = src[e + 1];
        const unsigned* kp0 = (const unsigned*)(g_kb + (size_t)sn0 * DD + off);
        const unsigned* vp0 = (const unsigned*)(g_vb + (size_t)sn0 * DD + off);
        const unsigned* kp1 = (const unsigned*)(g_kb + (size_t)sn1 * DD + off);
        const unsigned* vp1 = (const unsigned*)(g_vb + (size_t)sn1 * DD + off);
        unsigned vw0[3], vw1[3];
        float p0 = dot6(q0, q1, q2, kp0[0], kp0[1], kp0[2]);
        vw0[0] = vp0[0]; vw0[1] = vp0[1]; vw0[2] = vp0[2];
        float p1 = dot6(q0, q1, q2, kp1[0], kp1[1], kp1[2]);
        vw1[0] = vp1[0]; vw1[1] = vp1[1]; vw1[2] = vp1[2];
#pragma unroll
        for (int d = 1; d < 8; d <<= 1) {
            p0 += __shfl_xor_sync(0xffffffffu, p0, d);
            p1 += __shfl_xor_sync(0xffffffffu, p1, d);
        }
        float e0 = __expf(p0 * coef);
        float e1 = __expf(p1 * coef);
        l += e0 + e1;
#pragma unroll
        for (int j = 0; j < 3; j++) {
            float2 v0 = __bfloat1622float2(*(__nv_bfloat162*)&vw0[j]);
            float2 v1 = __bfloat1622float2(*(__nv_bfloat162*)&vw1[j]);
            acc[2 * j] += e0 * v0.x + e1 * v1.x;
            acc[2 * j + 1] += e0 * v0.y + e1 * v1.y;
        }
    }
    if (e < s1) {
        int sn = src[e];
        const unsigned* kp = (const unsigned*)(g_kb + (size_t)sn * DD + off);
        const unsigned* vp = (const unsigned*)(g_vb + (size_t)sn * DD + off);
        unsigned vw0 = vp[0], vw1 = vp[1], vw2 = vp[2];
        float p = dot6(q0, q1, q2, kp[0], kp[1], kp[2]);
#pragma unroll
        for (int d = 1; d < 8; d <<= 1) p += __shfl_xor_sync(0xffffffffu, p, d);
        float es = __expf(p * coef);
        l += es;
        float2 v0 = __bfloat1622float2(*(__nv_bfloat162*)&vw0);
        float2 v1 = __bfloat1622float2(*(__nv_bfloat162*)&vw1);
        float2 v2 = __bfloat1622float2(*(__nv_bfloat162*)&vw2);
        acc[0] += es * v0.x; acc[1] += es * v0.y;
        acc[2] += es * v1.x; acc[3] += es * v1.y;
        acc[4] += es * v2.x; acc[5] += es * v2.y;
    }
    float invl = (s1 > s0) ? (1.f / l) : 0.f;
    __nv_bfloat162* op = (__nv_bfloat162*)(g_aggb + (size_t)warp * DD + off);
#pragma unroll
    for (int j = 0; j < 3; j++)
        op[j] = __floats2bfloat162_rn(acc[2 * j] * invl, acc[2 * j + 1] * invl);
}

// ---------------- bf16 tensor-core GEMM: m16n8k16, 2-stage cp.async (R9 config) ----------------
#define BM 128
#define BN 64
#define BK 32
#define AKS 40
#define BKS 40

__device__ __forceinline__ void mma_bf16(float& c0, float& c1, float& c2, float& c3,
                                         unsigned a0, unsigned a1, unsigned a2, unsigned a3,
                                         unsigned b0, unsigned b1) {
    asm volatile(
        "mma.sync.aligned.m16n8k16.row.col.f32.bf16.bf16.f32 "
        "{%0,%1,%2,%3}, {%4,%5,%6,%7}, {%8,%9}, {%0,%1,%2,%3};"
        : "+f"(c0), "+f"(c1), "+f"(c2), "+f"(c3)
        : "r"(a0), "r"(a1), "r"(a2), "r"(a3), "r"(b0), "r"(b1));
}

// mode: 0 proj fp32, 1 gelu->bf16 mlp1, 2 residual->out fp32, 3 qkv scatter (all bf16)
__global__ void __launch_bounds__(256) gemm_kernel(
        const bf16* __restrict__ A, const bf16* __restrict__ Bt,
        const float* __restrict__ bias, float* __restrict__ out,
        const float* __restrict__ res, int M, int K, int Nc, int mode) {
    __shared__ bf16 As[2][BM][AKS];
    __shared__ bf16 Bs[2][BN][BKS];
    int tid = threadIdx.x;
    int lane = tid & 31;
    int wid = tid >> 5;
    int warp_m = wid & 3;
    int warp_n = wid >> 2;
    int m0 = blockIdx.y * BM;
    int n0 = blockIdx.x * BN;
    int gid = lane >> 2;
    int tig = lane & 3;

    int cp_row = tid >> 2;
    int cp_c = (tid & 3) * 8;

    float acc[2][4][4];
#pragma unroll
    for (int mt = 0; mt < 2; mt++)
#pragma unroll
        for (int nt = 0; nt < 4; nt++)
#pragma unroll
            for (int j = 0; j < 4; j++) acc[mt][nt][j] = 0.f;

    int niter = K / BK;

#define LOAD_STAGE(it, buf)                                                            \
    {                                                                                  \
        int k0s = (it) * BK;                                                           \
        _Pragma("unroll")                                                              \
        for (int i = 0; i < 2; i++) {                                                  \
            int row = cp_row + i * 64;                                                 \
            const bf16* srcp = A + (size_t)(m0 + row) * K + k0s + cp_c;                \
            unsigned dstp = (unsigned)__cvta_generic_to_shared(&As[buf][row][cp_c]);   \
            int sz = (m0 + row < M) ? 16 : 0;                                          \
            asm volatile("cp.async.cg.shared.global [%0], [%1], 16, %2;\n"             \
                         :: "r"(dstp), "l"(srcp), "r"(sz));                            \
        }                                                                              \
        {                                                                              \
            const bf16* srcp = Bt + (size_t)(n0 + cp_row) * K + k0s + cp_c;            \
            unsigned dstp = (unsigned)__cvta_generic_to_shared(&Bs[buf][cp_row][cp_c]); \
            asm volatile("cp.async.cg.shared.global [%0], [%1], 16;\n"                 \
                         :: "r"(dstp), "l"(srcp));                                     \
        }                                                                              \
        asm volatile("cp.async.commit_group;\n");                                      \
    }

    LOAD_STAGE(0, 0);

    for (int it = 0; it < niter; it++) {
        int buf = it & 1;
        asm volatile("cp.async.wait_group 0;\n" ::: "memory");
        __syncthreads();
        if (it + 1 < niter) LOAD_STAGE(it + 1, buf ^ 1);

#pragma unroll
        for (int kk = 0; kk < 2; kk++) {
            int w0 = kk * 8 + tig;
            unsigned a[2][4];
#pragma unroll
            for (int mt = 0; mt < 2; mt++) {
                int r = warp_m * 32 + mt * 16 + gid;
                const unsigned* r0 = (const unsigned*)&As[buf][r][0];
                const unsigned* r8 = (const unsigned*)&As[buf][r + 8][0];
                a[mt][0] = r0[w0];
                a[mt][1] = r8[w0];
                a[mt][2] = r0[w0 + 4];
                a[mt][3] = r8[w0 + 4];
            }
            unsigned b[4][2];
#pragma unroll
            for (int nt = 0; nt < 4; nt++) {
                int n = warp_n * 32 + nt * 8 + gid;
                const unsigned* rn = (const unsigned*)&Bs[buf][n][0];
                b[nt][0] = rn[w0];
                b[nt][1] = rn[w0 + 4];
            }
#pragma unroll
            for (int mt = 0; mt < 2; mt++)
#pragma unroll
                for (int nt = 0; nt < 4; nt++)
                    mma_bf16(acc[mt][nt][0], acc[mt][nt][1], acc[mt][nt][2], acc[mt][nt][3],
                             a[mt][0], a[mt][1], a[mt][2], a[mt][3],
                             b[nt][0], b[nt][1]);
        }
        __syncthreads();
    }

    // epilogue
#pragma unroll
    for (int mt = 0; mt < 2; mt++) {
#pragma unroll
        for (int nt = 0; nt < 4; nt++) {
#pragma unroll
            for (int half = 0; half < 2; half++) {
                int m = m0 + warp_m * 32 + mt * 16 + gid + half * 8;
                if (m >= M) continue;
#pragma unroll
                for (int j = 0; j < 2; j++) {
                    int n = n0 + warp_n * 32 + nt * 8 + 2 * tig + j;
                    float val = acc[mt][nt][half * 2 + j] + bias[n];
                    if (mode == 0) {
                        out[(size_t)m * Nc + n] = val;
                    } else if (mode == 1) {
                        g_mlp1b[(size_t)m * DFF + n] = __float2bfloat16_rn(val * normcdff(val));
                    } else if (mode == 2) {
                        out[(size_t)m * Nc + n] = val + res[(size_t)m * Nc + n];
                    } else {
                        int hh = n / 144;
                        int r = n - hh * 144;
                        int w = r / DHH;
                        int dd = r - w * DHH;
                        size_t o = (size_t)m * DD + hh * DHH + dd;
                        bf16 bv = __float2bfloat16_rn(val);
                        if (w == 0) g_qb[o] = bv;
                        else if (w == 1) g_kb[o] = bv;
                        else g_vb[o] = bv;
                    }
                }
            }
        }
    }
}

// ---------------- launch ----------------
static inline void* sym(const void* s) {
    void* p = nullptr;
    cudaGetSymbolAddress(&p, s);
    return p;
}

extern "C" void kernel_launch(void* const* d_in, const int* in_sizes, int n_in,
                              void* d_out, int out_size) {
    const float* x = (const float*)d_in[0];
    const void* mask = d_in[1];
    const int* src = (const int*)d_in[2];
    const int* dst = (const int*)d_in[3];
    const float* ln1_g = (const float*)d_in[4];
    const float* ln1_b = (const float*)d_in[5];
    const float* Wqkv = (const float*)d_in[6];
    const float* bqkv = (const float*)d_in[7];
    const float* Wout = (const float*)d_in[8];
    const float* bout = (const float*)d_in[9];
    const float* ln2_g = (const float*)d_in[10];
    const float* ln2_b = (const float*)d_in[11];
    const float* W1 = (const float*)d_in[12];
    const float* b1 = (const float*)d_in[13];
    const float* W2 = (const float*)d_in[14];
    const float* b2 = (const float*)d_in[15];
    float* out = (float*)d_out;

    bf16* hnb = (bf16*)sym(g_hnb);
    bf16* aggb = (bf16*)sym(g_aggb);
    float* proj = (float*)sym(g_proj);
    float* t1 = (float*)sym(g_t1);
    bf16* hn2b = (bf16*)sym(g_hn2b);
    bf16* mlp1b = (bf16*)sym(g_mlp1b);
    bf16* wqkvT = (bf16*)sym(g_wqkvT);
    bf16* woutT = (bf16*)sym(g_woutT);
    bf16* w1T = (bf16*)sym(g_w1T);
    bf16* w2T = (bf16*)sym(g_w2T);

    // 0. prep: weight transposes (sets mask flag), then detect
    {
        int total = DD * D3 + DD * DD + DD * DFF + DFF * DD;
        wtrans_all_kernel<<<(total + 255) / 256, 256>>>(Wqkv, Wout, W1, W2);
    }
    detect_mask_kernel<<<(NN / 4 + 255) / 256, 256>>>((const unsigned*)mask);

    // 1. permutation scan
    blockscan_kernel<<<NB, 1024>>>(mask);
    scan_sums_kernel<<<1, 128>>>();

    // 2. LN1 fused with rank computation + gather -> bf16 (also writes g_inv)
    ln_rank_kernel<<<(NN + 7) / 8, 256>>>(x, ln1_g, ln1_b, mask);

    // 3. CSR offsets
    rowstart_kernel<<<(EE + 255) / 256, 256>>>(dst);

    // 4. QKV GEMM (scatter epilogue, all bf16)
    {
        dim3 grid(D3 / BN, (NN + BM - 1) / BM);
        gemm_kernel<<<grid, 256>>>(hnb, wqkvT, bqkv, nullptr, nullptr, NN, DD, D3, 3);
    }

    // 5. graph attention -> bf16 agg
    attn_kernel<<<(NN * 32 + 255) / 256, 256>>>(src);

    // 6. out-projection -> fp32 proj
    {
        dim3 grid(DD / BN, (NN + BM - 1) / BM);
        gemm_kernel<<<grid, 256>>>(aggb, woutT, bout, proj, nullptr, NN, DD, DD, 0);
    }

    // 7. fused residual + unpermute + LN2
    resln_kernel<<<(NN + 7) / 8, 256>>>(x, ln2_g, ln2_b);

    // 8. MLP up + GELU -> bf16 mlp1
    {
        dim3 grid(DFF / BN, (NN + BM - 1) / BM);
        gemm_kernel<<<grid, 256>>>(hn2b, w1T, b1, nullptr, nullptr, NN, DD, DFF, 1);
    }

    // 9. MLP down + residual -> out fp32
    {
        dim3 grid(DD / BN, (NN + BM - 1) / BM);
        gemm_kernel<<<grid, 256>>>(mlp1b, w2T, b2, out, t1, NN, DFF, DD, 2);
    }
}

// round 14
// speedup vs baseline: 1.0091x; 1.0024x over previous
#include <cuda_runtime.h>
#include <cuda_bf16.h>
#include <math_constants.h>

#define NN 100000
#define EE 1600000
#define DD 192
#define HH 4
#define DHH 48
#define D3 576
#define DFF 384
#define NB 98
#define PAD 256   // padded row: 32 slots x 8 bf16 (6 used + 2 pad)

typedef __nv_bfloat16 bf16;

// ---------------- scratch ----------------
__device__ int g_is_int32;
__device__ int g_prefix[NN];
__device__ int g_bsum[NB];
__device__ int g_boff[NB];
__device__ int g_T;
__device__ int g_inv[NN];
__device__ int g_rowstart[NN + 1];
__device__ bf16 g_hnb[(size_t)NN * DD];
__device__ bf16 g_qp[(size_t)NN * PAD];   // padded q
__device__ bf16 g_kp[(size_t)NN * PAD];   // padded k
__device__ bf16 g_vp[(size_t)NN * PAD];   // padded v
__device__ bf16 g_aggb[(size_t)NN * DD];
__device__ float g_proj[(size_t)NN * DD];
__device__ float g_t1[(size_t)NN * DD];
__device__ bf16 g_hn2b[(size_t)NN * DD];
__device__ bf16 g_mlp1b[(size_t)NN * DFF];
__device__ bf16 g_wqkvT[(size_t)D3 * DD];
__device__ bf16 g_woutT[(size_t)DD * DD];
__device__ bf16 g_w1T[(size_t)DFF * DD];
__device__ bf16 g_w2T[(size_t)DD * DFF];

__device__ __forceinline__ int read_mask(const void* mask, int i) {
    if (g_is_int32) return ((const int*)mask)[i] != 0;
    return ((const unsigned char*)mask)[i] != 0;
}

// ---------------- fused weight transpose + flag init ----------------
__global__ void wtrans_all_kernel(const float* __restrict__ Wqkv, const float* __restrict__ Wout,
                                  const float* __restrict__ W1, const float* __restrict__ W2) {
    const int S0 = DD * D3;
    const int S1 = S0 + DD * DD;
    const int S2 = S1 + DD * DFF;
    const int S3 = S2 + DFF * DD;
    int idx = blockIdx.x * blockDim.x + threadIdx.x;
    if (idx == 0) g_is_int32 = 1;
    if (idx >= S3) return;
    const float* W; bf16* Wt; int K, Nw, local;
    if (idx < S0) { W = Wqkv; Wt = g_wqkvT; K = DD; Nw = D3; local = idx; }
    else if (idx < S1) { W = Wout; Wt = g_woutT; K = DD; Nw = DD; local = idx - S0; }
    else if (idx < S2) { W = W1; Wt = g_w1T; K = DD; Nw = DFF; local = idx - S1; }
    else { W = W2; Wt = g_w2T; K = DFF; Nw = DD; local = idx - S2; }
    int n = local / K;
    int k = local - n * K;
    Wt[local] = __float2bfloat16_rn(W[(size_t)k * Nw + n]);
}

__global__ void detect_mask_kernel(const unsigned* __restrict__ m) {
    int i = blockIdx.x * blockDim.x + threadIdx.x;
    if (i >= NN / 4) return;
    if (m[i] > 1u) atomicExch(&g_is_int32, 0);
}

// ---------------- multi-block scan ----------------
__global__ void blockscan_kernel(const void* __restrict__ mask) {
    int tid = threadIdx.x;
    int i = blockIdx.x * 1024 + tid;
    int v = (i < NN) ? read_mask(mask, i) : 0;
    int lane = tid & 31, wid = tid >> 5;
    int s = v;
#pragma unroll
    for (int off = 1; off < 32; off <<= 1) {
        int t = __shfl_up_sync(0xffffffffu, s, off);
        if (lane >= off) s += t;
    }
    __shared__ int wsum[32];
    if (lane == 31) wsum[wid] = s;
    __syncthreads();
    if (wid == 0) {
        int ws = wsum[lane];
#pragma unroll
        for (int off = 1; off < 32; off <<= 1) {
            int t = __shfl_up_sync(0xffffffffu, ws, off);
            if (lane >= off) ws += t;
        }
        wsum[lane] = ws;
    }
    __syncthreads();
    int incl = s + (wid > 0 ? wsum[wid - 1] : 0);
    if (i < NN) g_prefix[i] = incl;
    if (tid == 1023) g_bsum[blockIdx.x] = incl;
}

__global__ void scan_sums_kernel() {
    int tid = threadIdx.x;
    int v = (tid < NB) ? g_bsum[tid] : 0;
    int lane = tid & 31, wid = tid >> 5;
    int s = v;
#pragma unroll
    for (int off = 1; off < 32; off <<= 1) {
        int t = __shfl_up_sync(0xffffffffu, s, off);
        if (lane >= off) s += t;
    }
    __shared__ int wsum[4];
    if (lane == 31) wsum[wid] = s;
    __syncthreads();
    int add = 0;
    for (int w = 0; w < wid; w++) add += wsum[w];
    int incl = s + add;
    if (tid < NB) g_boff[tid] = incl - v;
    if (tid == NB - 1) g_T = incl;
}

// ---------------- LN1 fused with rank computation + gather, bf16 output ----------------
__global__ void ln_rank_kernel(const float* __restrict__ in, const float* __restrict__ g,
                               const float* __restrict__ b, const void* __restrict__ mask) {
    int row = blockIdx.x * 8 + (threadIdx.x >> 5);
    if (row >= NN) return;
    int lane = threadIdx.x & 31;
    int inc = g_prefix[row] + g_boff[row >> 10];
    int r = read_mask(mask, row) ? (inc - 1) : (g_T + row - inc);
    if (lane == 0) g_inv[r] = row;
    const float* p = in + (size_t)r * DD;
    float vals[6];
    float s = 0.f;
#pragma unroll
    for (int j = 0; j < 6; j++) { vals[j] = p[lane + j * 32]; s += vals[j]; }
#pragma unroll
    for (int off = 16; off > 0; off >>= 1) s += __shfl_xor_sync(0xffffffffu, s, off);
    float mu = s * (1.f / DD);
    float vs = 0.f;
#pragma unroll
    for (int j = 0; j < 6; j++) { float d = vals[j] - mu; vs += d * d; }
#pragma unroll
    for (int off = 16; off > 0; off >>= 1) vs += __shfl_xor_sync(0xffffffffu, vs, off);
    float rr = rsqrtf(vs * (1.f / DD) + 1e-5f);
    bf16* o = g_hnb + (size_t)row * DD;
#pragma unroll
    for (int j = 0; j < 6; j++) {
        int c = lane + j * 32;
        o[c] = __float2bfloat16_rn((vals[j] - mu) * rr * g[c] + b[c]);
    }
}

// ---------------- fused residual+unpermute+LN2 ----------------
__global__ void resln_kernel(const float* __restrict__ x, const float* __restrict__ g,
                             const float* __restrict__ b) {
    int row = blockIdx.x * 8 + (threadIdx.x >> 5);
    if (row >= NN) return;
    int lane = threadIdx.x & 31;
    const float* xp = x + (size_t)row * DD;
    const float* pp = g_proj + (size_t)g_inv[row] * DD;
    float* t1p = g_t1 + (size_t)row * DD;
    float vals[6];
    float s = 0.f;
#pragma unroll
    for (int j = 0; j < 6; j++) {
        int c = lane + j * 32;
        vals[j] = xp[c] + pp[c];
        t1p[c] = vals[j];
        s += vals[j];
    }
#pragma unroll
    for (int off = 16; off > 0; off >>= 1) s += __shfl_xor_sync(0xffffffffu, s, off);
    float mu = s * (1.f / DD);
    float vs = 0.f;
#pragma unroll
    for (int j = 0; j < 6; j++) { float d = vals[j] - mu; vs += d * d; }
#pragma unroll
    for (int off = 16; off > 0; off >>= 1) vs += __shfl_xor_sync(0xffffffffu, vs, off);
    float r = rsqrtf(vs * (1.f / DD) + 1e-5f);
    bf16* o = g_hn2b + (size_t)row * DD;
#pragma unroll
    for (int j = 0; j < 6; j++) {
        int c = lane + j * 32;
        o[c] = __float2bfloat16_rn((vals[j] - mu) * r * g[c] + b[c]);
    }
}

// ---------------- CSR row offsets ----------------
__global__ void rowstart_kernel(const int* __restrict__ dst) {
    int e = blockIdx.x * blockDim.x + threadIdx.x;
    if (e >= EE) return;
    int cur = dst[e];
    int prev = (e == 0) ? -1 : dst[e - 1];
    for (int n = prev + 1; n <= cur; n++) g_rowstart[n] = e;
    if (e == EE - 1) {
        for (int n = cur + 1; n <= NN; n++) g_rowstart[n] = EE;
    }
}

// ---------------- graph attention: padded layout, 1x LDG.128 per k/v row-slot ----------------
__device__ __forceinline__ float dot6(float2 q0, float2 q1, float2 q2,
                                      unsigned k0, unsigned k1, unsigned k2) {
    float2 a = __bfloat1622float2(*(__nv_bfloat162*)&k0);
    float2 b = __bfloat1622float2(*(__nv_bfloat162*)&k1);
    float2 c = __bfloat1622float2(*(__nv_bfloat162*)&k2);
    return q0.x * a.x + q0.y * a.y + q1.x * b.x + q1.y * b.y + q2.x * c.x + q2.y * c.y;
}

__global__ void attn_kernel(const int* __restrict__ src) {
    int warp = (blockIdx.x * blockDim.x + threadIdx.x) >> 5;
    if (warp >= NN) return;
    int lane = threadIdx.x & 31;
    int slot = lane * 8;                       // padded bf16 offset (16B per lane)
    uint4 qv = *(const uint4*)(g_qp + (size_t)warp * PAD + slot);
    float2 q0 = __bfloat1622float2(*(__nv_bfloat162*)&qv.x);
    float2 q1 = __bfloat1622float2(*(__nv_bfloat162*)&qv.y);
    float2 q2 = __bfloat1622float2(*(__nv_bfloat162*)&qv.z);

    int s0 = g_rowstart[warp];
    int s1 = g_rowstart[warp + 1];
    const float coef = 0.14433756729740643f;
    float l = 0.f;
    float acc[6] = {0.f, 0.f, 0.f, 0.f, 0.f, 0.f};

    int e = s0;
    for (; e + 1 < s1; e += 2) {
        int sn0 = src[e], sn1 = src[e + 1];
        uint4 k0v = *(const uint4*)(g_kp + (size_t)sn0 * PAD + slot);
        uint4 v0v = *(const uint4*)(g_vp + (size_t)sn0 * PAD + slot);
        uint4 k1v = *(const uint4*)(g_kp + (size_t)sn1 * PAD + slot);
        uint4 v1v = *(const uint4*)(g_vp + (size_t)sn1 * PAD + slot);
        float p0 = dot6(q0, q1, q2, k0v.x, k0v.y, k0v.z);
        float p1 = dot6(q0, q1, q2, k1v.x, k1v.y, k1v.z);
#pragma unroll
        for (int d = 1; d < 8; d <<= 1) {
            p0 += __shfl_xor_sync(0xffffffffu, p0, d);
            p1 += __shfl_xor_sync(0xffffffffu, p1, d);
        }
        float e0 = __expf(p0 * coef);
        float e1 = __expf(p1 * coef);
        l += e0 + e1;
        {
            float2 a0 = __bfloat1622float2(*(__nv_bfloat162*)&v0v.x);
            float2 a1 = __bfloat1622float2(*(__nv_bfloat162*)&v1v.x);
            acc[0] += e0 * a0.x + e1 * a1.x;
            acc[1] += e0 * a0.y + e1 * a1.y;
            float2 b0 = __bfloat1622float2(*(__nv_bfloat162*)&v0v.y);
            float2 b1 = __bfloat1622float2(*(__nv_bfloat162*)&v1v.y);
            acc[2] += e0 * b0.x + e1 * b1.x;
            acc[3] += e0 * b0.y + e1 * b1.y;
            float2 c0 = __bfloat1622float2(*(__nv_bfloat162*)&v0v.z);
            float2 c1 = __bfloat1622float2(*(__nv_bfloat162*)&v1v.z);
            acc[4] += e0 * c0.x + e1 * c1.x;
            acc[5] += e0 * c0.y + e1 * c1.y;
        }
    }
    if (e < s1) {
        int sn = src[e];
        uint4 kv = *(const uint4*)(g_kp + (size_t)sn * PAD + slot);
        uint4 vv = *(const uint4*)(g_vp + (size_t)sn * PAD + slot);
        float p = dot6(q0, q1, q2, kv.x, kv.y, kv.z);
#pragma unroll
        for (int d = 1; d < 8; d <<= 1) p += __shfl_xor_sync(0xffffffffu, p, d);
        float es = __expf(p * coef);
        l += es;
        float2 a = __bfloat1622float2(*(__nv_bfloat162*)&vv.x);
        float2 b = __bfloat1622float2(*(__nv_bfloat162*)&vv.y);
        float2 c = __bfloat1622float2(*(__nv_bfloat162*)&vv.z);
        acc[0] += es * a.x; acc[1] += es * a.y;
        acc[2] += es * b.x; acc[3] += es * b.y;
        acc[4] += es * c.x; acc[5] += es * c.y;
    }
    float invl = (s1 > s0) ? (1.f / l) : 0.f;
    // compact agg output: off = head*48 + sub*6 (byte offset divisible by 4)
    int off = (lane >> 3) * DHH + (lane & 7) * 6;
    __nv_bfloat162* op = (__nv_bfloat162*)(g_aggb + (size_t)warp * DD + off);
#pragma unroll
    for (int j = 0; j < 3; j++)
        op[j] = __floats2bfloat162_rn(acc[2 * j] * invl, acc[2 * j + 1] * invl);
}

// ---------------- bf16 tensor-core GEMM: m16n8k16, 2-stage cp.async (R9 config) ----------------
#define BM 128
#define BN 64
#define BK 32
#define AKS 40
#define BKS 40

__device__ __forceinline__ void mma_bf16(float& c0, float& c1, float& c2, float& c3,
                                         unsigned a0, unsigned a1, unsigned a2, unsigned a3,
                                         unsigned b0, unsigned b1) {
    asm volatile(
        "mma.sync.aligned.m16n8k16.row.col.f32.bf16.bf16.f32 "
        "{%0,%1,%2,%3}, {%4,%5,%6,%7}, {%8,%9}, {%0,%1,%2,%3};"
        : "+f"(c0), "+f"(c1), "+f"(c2), "+f"(c3)
        : "r"(a0), "r"(a1), "r"(a2), "r"(a3), "r"(b0), "r"(b1));
}

// mode: 0 proj fp32, 1 gelu->bf16 mlp1, 2 residual->out fp32, 3 qkv scatter (padded bf16)
__global__ void __launch_bounds__(256) gemm_kernel(
        const bf16* __restrict__ A, const bf16* __restrict__ Bt,
        const float* __restrict__ bias, float* __restrict__ out,
        const float* __restrict__ res, int M, int K, int Nc, int mode) {
    __shared__ bf16 As[2][BM][AKS];
    __shared__ bf16 Bs[2][BN][BKS];
    int tid = threadIdx.x;
    int lane = tid & 31;
    int wid = tid >> 5;
    int warp_m = wid & 3;
    int warp_n = wid >> 2;
    int m0 = blockIdx.y * BM;
    int n0 = blockIdx.x * BN;
    int gid = lane >> 2;
    int tig = lane & 3;

    int cp_row = tid >> 2;
    int cp_c = (tid & 3) * 8;

    float acc[2][4][4];
#pragma unroll
    for (int mt = 0; mt < 2; mt++)
#pragma unroll
        for (int nt = 0; nt < 4; nt++)
#pragma unroll
            for (int j = 0; j < 4; j++) acc[mt][nt][j] = 0.f;

    int niter = K / BK;

#define LOAD_STAGE(it, buf)                                                            \
    {                                                                                  \
        int k0s = (it) * BK;                                                           \
        _Pragma("unroll")                                                              \
        for (int i = 0; i < 2; i++) {                                                  \
            int row = cp_row + i * 64;                                                 \
            const bf16* srcp = A + (size_t)(m0 + row) * K + k0s + cp_c;                \
            unsigned dstp = (unsigned)__cvta_generic_to_shared(&As[buf][row][cp_c]);   \
            int sz = (m0 + row < M) ? 16 : 0;                                          \
            asm volatile("cp.async.cg.shared.global [%0], [%1], 16, %2;\n"             \
                         :: "r"(dstp), "l"(srcp), "r"(sz));                            \
        }                                                                              \
        {                                                                              \
            const bf16* srcp = Bt + (size_t)(n0 + cp_row) * K + k0s + cp_c;            \
            unsigned dstp = (unsigned)__cvta_generic_to_shared(&Bs[buf][cp_row][cp_c]); \
            asm volatile("cp.async.cg.shared.global [%0], [%1], 16;\n"                 \
                         :: "r"(dstp), "l"(srcp));                                     \
        }                                                                              \
        asm volatile("cp.async.commit_group;\n");                                      \
    }

    LOAD_STAGE(0, 0);

    for (int it = 0; it < niter; it++) {
        int buf = it & 1;
        asm volatile("cp.async.wait_group 0;\n" ::: "memory");
        __syncthreads();
        if (it + 1 < niter) LOAD_STAGE(it + 1, buf ^ 1);

#pragma unroll
        for (int kk = 0; kk < 2; kk++) {
            int w0 = kk * 8 + tig;
            unsigned a[2][4];
#pragma unroll
            for (int mt = 0; mt < 2; mt++) {
                int r = warp_m * 32 + mt * 16 + gid;
                const unsigned* r0 = (const unsigned*)&As[buf][r][0];
                const unsigned* r8 = (const unsigned*)&As[buf][r + 8][0];
                a[mt][0] = r0[w0];
                a[mt][1] = r8[w0];
                a[mt][2] = r0[w0 + 4];
                a[mt][3] = r8[w0 + 4];
            }
            unsigned b[4][2];
#pragma unroll
            for (int nt = 0; nt < 4; nt++) {
                int n = warp_n * 32 + nt * 8 + gid;
                const unsigned* rn = (const unsigned*)&Bs[buf][n][0];
                b[nt][0] = rn[w0];
                b[nt][1] = rn[w0 + 4];
            }
#pragma unroll
            for (int mt = 0; mt < 2; mt++)
#pragma unroll
                for (int nt = 0; nt < 4; nt++)
                    mma_bf16(acc[mt][nt][0], acc[mt][nt][1], acc[mt][nt][2], acc[mt][nt][3],
                             a[mt][0], a[mt][1], a[mt][2], a[mt][3],
                             b[nt][0], b[nt][1]);
        }
        __syncthreads();
    }

    // epilogue
#pragma unroll
    for (int mt = 0; mt < 2; mt++) {
#pragma unroll
        for (int nt = 0; nt < 4; nt++) {
#pragma unroll
            for (int half = 0; half < 2; half++) {
                int m = m0 + warp_m * 32 + mt * 16 + gid + half * 8;
                if (m >= M) continue;
#pragma unroll
                for (int j = 0; j < 2; j++) {
                    int n = n0 + warp_n * 32 + nt * 8 + 2 * tig + j;
                    float val = acc[mt][nt][half * 2 + j] + bias[n];
                    if (mode == 0) {
                        out[(size_t)m * Nc + n] = val;
                    } else if (mode == 1) {
                        g_mlp1b[(size_t)m * DFF + n] = __float2bfloat16_rn(val * normcdff(val));
                    } else if (mode == 2) {
                        out[(size_t)m * Nc + n] = val + res[(size_t)m * Nc + n];
                    } else {
                        // padded scatter: lane slot = head*8 + dd/6, pos = dd%6
                        int hh = n / 144;
                        int r = n - hh * 144;
                        int w = r / DHH;
                        int dd = r - w * DHH;
                        size_t o = (size_t)m * PAD + (hh * 8 + dd / 6) * 8 + (dd - (dd / 6) * 6);
                        bf16 bv = __float2bfloat16_rn(val);
                        if (w == 0) g_qp[o] = bv;
                        else if (w == 1) g_kp[o] = bv;
                        else g_vp[o] = bv;
                    }
                }
            }
        }
    }
}

// ---------------- launch ----------------
static inline void* sym(const void* s) {
    void* p = nullptr;
    cudaGetSymbolAddress(&p, s);
    return p;
}

extern "C" void kernel_launch(void* const* d_in, const int* in_sizes, int n_in,
                              void* d_out, int out_size) {
    const float* x = (const float*)d_in[0];
    const void* mask = d_in[1];
    const int* src = (const int*)d_in[2];
    const int* dst = (const int*)d_in[3];
    const float* ln1_g = (const float*)d_in[4];
    const float* ln1_b = (const float*)d_in[5];
    const float* Wqkv = (const float*)d_in[6];
    const float* bqkv = (const float*)d_in[7];
    const float* Wout = (const float*)d_in[8];
    const float* bout = (const float*)d_in[9];
    const float* ln2_g = (const float*)d_in[10];
    const float* ln2_b = (const float*)d_in[11];
    const float* W1 = (const float*)d_in[12];
    const float* b1 = (const float*)d_in[13];
    const float* W2 = (const float*)d_in[14];
    const float* b2 = (const float*)d_in[15];
    float* out = (float*)d_out;

    bf16* hnb = (bf16*)sym(g_hnb);
    bf16* aggb = (bf16*)sym(g_aggb);
    float* proj = (float*)sym(g_proj);
    float* t1 = (float*)sym(g_t1);
    bf16* hn2b = (bf16*)sym(g_hn2b);
    bf16* mlp1b = (bf16*)sym(g_mlp1b);
    bf16* wqkvT = (bf16*)sym(g_wqkvT);
    bf16* woutT = (bf16*)sym(g_woutT);
    bf16* w1T = (bf16*)sym(g_w1T);
    bf16* w2T = (bf16*)sym(g_w2T);

    // 0. prep: weight transposes (sets mask flag), then detect
    {
        int total = DD * D3 + DD * DD + DD * DFF + DFF * DD;
        wtrans_all_kernel<<<(total + 255) / 256, 256>>>(Wqkv, Wout, W1, W2);
    }
    detect_mask_kernel<<<(NN / 4 + 255) / 256, 256>>>((const unsigned*)mask);

    // 1. permutation scan
    blockscan_kernel<<<NB, 1024>>>(mask);
    scan_sums_kernel<<<1, 128>>>();

    // 2. LN1 fused with rank computation + gather -> bf16 (also writes g_inv)
    ln_rank_kernel<<<(NN + 7) / 8, 256>>>(x, ln1_g, ln1_b, mask);

    // 3. CSR offsets
    rowstart_kernel<<<(EE + 255) / 256, 256>>>(dst);

    // 4. QKV GEMM (padded scatter epilogue)
    {
        dim3 grid(D3 / BN, (NN + BM - 1) / BM);
        gemm_kernel<<<grid, 256>>>(hnb, wqkvT, bqkv, nullptr, nullptr, NN, DD, D3, 3);
    }

    // 5. graph attention (padded k/v, LDG.128 per slot) -> compact bf16 agg
    attn_kernel<<<(NN * 32 + 255) / 256, 256>>>(src);

    // 6. out-projection -> fp32 proj
    {
        dim3 grid(DD / BN, (NN + BM - 1) / BM);
        gemm_kernel<<<grid, 256>>>(aggb, woutT, bout, proj, nullptr, NN, DD, DD, 0);
    }

    // 7. fused residual + unpermute + LN2
    resln_kernel<<<(NN + 7) / 8, 256>>>(x, ln2_g, ln2_b);

    // 8. MLP up + GELU -> bf16 mlp1
    {
        dim3 grid(DFF / BN, (NN + BM - 1) / BM);
        gemm_kernel<<<grid, 256>>>(hn2b, w1T, b1, nullptr, nullptr, NN, DD, DFF, 1);
    }

    // 9. MLP down + residual -> out fp32
    {
        dim3 grid(DD / BN, (NN + BM - 1) / BM);
        gemm_kernel<<<grid, 256>>>(mlp1b, w2T, b2, out, t1, NN, DFF, DD, 2);
    }
}

// round 16
// speedup vs baseline: 1.0285x; 1.0192x over previous
#include <cuda_runtime.h>
#include <cuda_bf16.h>
#include <math_constants.h>

#define NN 100000
#define EE 1600000
#define DD 192
#define HH 4
#define DHH 48
#define D3 576
#define DFF 384
#define NB 98

typedef __nv_bfloat16 bf16;

// ---------------- scratch ----------------
__device__ int g_is_int32;
__device__ int g_prefix[NN];
__device__ int g_bsum[NB];
__device__ int g_boff[NB];
__device__ int g_T;
__device__ int g_order[NN];
__device__ int g_inv[NN];
__device__ int g_rowstart[NN + 1];
__device__ bf16 g_hnb[(size_t)NN * DD];        // LN1 output (GEMM A)
__device__ float g_q[(size_t)NN * DD];
__device__ bf16 g_kb[(size_t)NN * DD];
__device__ bf16 g_vb[(size_t)NN * DD];
__device__ bf16 g_aggb[(size_t)NN * DD];       // attn output (GEMM A)
__device__ float g_proj[(size_t)NN * DD];
__device__ float g_t1[(size_t)NN * DD];
__device__ bf16 g_hn2b[(size_t)NN * DD];       // LN2 output (GEMM A)
__device__ bf16 g_mlp1b[(size_t)NN * DFF];     // GELU output (GEMM A)
// transposed bf16 weights: Wt[n][k]
__device__ bf16 g_wqkvT[(size_t)D3 * DD];
__device__ bf16 g_woutT[(size_t)DD * DD];
__device__ bf16 g_w1T[(size_t)DFF * DD];
__device__ bf16 g_w2T[(size_t)DD * DFF];

__device__ __forceinline__ int read_mask(const void* mask, int i) {
    if (g_is_int32) return ((const int*)mask)[i] != 0;
    return ((const unsigned char*)mask)[i] != 0;
}

// ---------------- mask dtype detection ----------------
__global__ void init_flag_kernel() { g_is_int32 = 1; }
__global__ void detect_mask_kernel(const unsigned* __restrict__ m) {
    int i = blockIdx.x * blockDim.x + threadIdx.x;
    if (i >= NN / 4) return;
    if (m[i] > 1u) atomicExch(&g_is_int32, 0);
}

// ---------------- weight transpose + bf16 convert: Wt[n][k] = W[k][n] ----------------
__global__ void wtrans_kernel(const float* __restrict__ W, bf16* __restrict__ Wt,
                              int K, int N) {
    int idx = blockIdx.x * blockDim.x + threadIdx.x;
    if (idx >= K * N) return;
    int n = idx / K;
    int k = idx - n * K;
    Wt[idx] = __float2bfloat16_rn(W[(size_t)k * N + n]);
}

// ---------------- multi-block scan ----------------
__global__ void blockscan_kernel(const void* __restrict__ mask) {
    int tid = threadIdx.x;
    int i = blockIdx.x * 1024 + tid;
    int v = (i < NN) ? read_mask(mask, i) : 0;
    int lane = tid & 31, wid = tid >> 5;
    int s = v;
#pragma unroll
    for (int off = 1; off < 32; off <<= 1) {
        int t = __shfl_up_sync(0xffffffffu, s, off);
        if (lane >= off) s += t;
    }
    __shared__ int wsum[32];
    if (lane == 31) wsum[wid] = s;
    __syncthreads();
    if (wid == 0) {
        int ws = wsum[lane];
#pragma unroll
        for (int off = 1; off < 32; off <<= 1) {
            int t = __shfl_up_sync(0xffffffffu, ws, off);
            if (lane >= off) ws += t;
        }
        wsum[lane] = ws;
    }
    __syncthreads();
    int incl = s + (wid > 0 ? wsum[wid - 1] : 0);
    if (i < NN) g_prefix[i] = incl;
    if (tid == 1023) g_bsum[blockIdx.x] = incl;
}

__global__ void scan_sums_kernel() {
    int tid = threadIdx.x;
    int v = (tid < NB) ? g_bsum[tid] : 0;
    int lane = tid & 31, wid = tid >> 5;
    int s = v;
#pragma unroll
    for (int off = 1; off < 32; off <<= 1) {
        int t = __shfl_up_sync(0xffffffffu, s, off);
        if (lane >= off) s += t;
    }
    __shared__ int wsum[4];
    if (lane == 31) wsum[wid] = s;
    __syncthreads();
    int add = 0;
    for (int w = 0; w < wid; w++) add += wsum[w];
    int incl = s + add;
    if (tid < NB) g_boff[tid] = incl - v;
    if (tid == NB - 1) g_T = incl;
}

__global__ void ranks_kernel(const void* __restrict__ mask) {
    int i = blockIdx.x * blockDim.x + threadIdx.x;
    if (i >= NN) return;
    int inc = g_prefix[i] + g_boff[i >> 10];
    int T = g_T;
    int r = read_mask(mask, i) ? (inc - 1) : (T + i - inc);
    g_order[i] = r;
    g_inv[r] = i;
}

// ---------------- LN1 with row gather, bf16 output ----------------
__global__ void ln_kernel(const float* __restrict__ in, const float* __restrict__ g,
                          const float* __restrict__ b) {
    int row = blockIdx.x * 8 + (threadIdx.x >> 5);
    if (row >= NN) return;
    int lane = threadIdx.x & 31;
    const float* p = in + (size_t)g_order[row] * DD;
    float vals[6];
    float s = 0.f;
#pragma unroll
    for (int j = 0; j < 6; j++) { vals[j] = p[lane + j * 32]; s += vals[j]; }
#pragma unroll
    for (int off = 16; off > 0; off >>= 1) s += __shfl_xor_sync(0xffffffffu, s, off);
    float mu = s * (1.f / DD);
    float vs = 0.f;
#pragma unroll
    for (int j = 0; j < 6; j++) { float d = vals[j] - mu; vs += d * d; }
#pragma unroll
    for (int off = 16; off > 0; off >>= 1) vs += __shfl_xor_sync(0xffffffffu, vs, off);
    float r = rsqrtf(vs * (1.f / DD) + 1e-5f);
    bf16* o = g_hnb + (size_t)row * DD;
#pragma unroll
    for (int j = 0; j < 6; j++) {
        int c = lane + j * 32;
        o[c] = __float2bfloat16_rn((vals[j] - mu) * r * g[c] + b[c]);
    }
}

// ---------------- fused residual+unpermute+LN2 (t1 fp32, hn2 bf16) ----------------
__global__ void resln_kernel(const float* __restrict__ x, const float* __restrict__ g,
                             const float* __restrict__ b) {
    int row = blockIdx.x * 8 + (threadIdx.x >> 5);
    if (row >= NN) return;
    int lane = threadIdx.x & 31;
    const float* xp = x + (size_t)row * DD;
    const float* pp = g_proj + (size_t)g_inv[row] * DD;
    float* t1p = g_t1 + (size_t)row * DD;
    float vals[6];
    float s = 0.f;
#pragma unroll
    for (int j = 0; j < 6; j++) {
        int c = lane + j * 32;
        vals[j] = xp[c] + pp[c];
        t1p[c] = vals[j];
        s += vals[j];
    }
#pragma unroll
    for (int off = 16; off > 0; off >>= 1) s += __shfl_xor_sync(0xffffffffu, s, off);
    float mu = s * (1.f / DD);
    float vs = 0.f;
#pragma unroll
    for (int j = 0; j < 6; j++) { float d = vals[j] - mu; vs += d * d; }
#pragma unroll
    for (int off = 16; off > 0; off >>= 1) vs += __shfl_xor_sync(0xffffffffu, vs, off);
    float r = rsqrtf(vs * (1.f / DD) + 1e-5f);
    bf16* o = g_hn2b + (size_t)row * DD;
#pragma unroll
    for (int j = 0; j < 6; j++) {
        int c = lane + j * 32;
        o[c] = __float2bfloat16_rn((vals[j] - mu) * r * g[c] + b[c]);
    }
}

// ---------------- CSR row offsets ----------------
__global__ void rowstart_kernel(const int* __restrict__ dst) {
    int e = blockIdx.x * blockDim.x + threadIdx.x;
    if (e >= EE) return;
    int cur = dst[e];
    int prev = (e == 0) ? -1 : dst[e - 1];
    for (int n = prev + 1; n <= cur; n++) g_rowstart[n] = e;
    if (e == EE - 1) {
        for (int n = cur + 1; n <= NN; n++) g_rowstart[n] = EE;
    }
}

// ---------------- graph attention (bf16 k/v, no-max softmax, bf16 agg out) ----------------
__global__ void attn_kernel(const int* __restrict__ src) {
    int warp = (blockIdx.x * blockDim.x + threadIdx.x) >> 5;
    if (warp >= NN) return;
    int lane = threadIdx.x & 31;
    int off = (lane >> 3) * DHH + (lane & 7) * 6;
    const float* qp = g_q + (size_t)warp * DD + off;
    float qr[6];
#pragma unroll
    for (int j = 0; j < 6; j++) qr[j] = qp[j];

    int s0 = g_rowstart[warp];
    int s1 = g_rowstart[warp + 1];
    const float coef = 0.14433756729740643f;
    float l = 0.f;
    float acc[6] = {0.f, 0.f, 0.f, 0.f, 0.f, 0.f};

    int e = s0;
    for (; e + 1 < s1; e += 2) {
        int sa = src[e], sb = src[e + 1];
        const __nv_bfloat162* ka = (const __nv_bfloat162*)(g_kb + (size_t)sa * DD + off);
        const __nv_bfloat162* va = (const __nv_bfloat162*)(g_vb + (size_t)sa * DD + off);
        const __nv_bfloat162* kb = (const __nv_bfloat162*)(g_kb + (size_t)sb * DD + off);
        const __nv_bfloat162* vb = (const __nv_bfloat162*)(g_vb + (size_t)sb * DD + off);
        float va_f[6], vb_f[6];
        float pa = 0.f, pb = 0.f;
#pragma unroll
        for (int j = 0; j < 3; j++) {
            float2 kaf = __bfloat1622float2(ka[j]);
            float2 kbf = __bfloat1622float2(kb[j]);
            float2 vaf = __bfloat1622float2(va[j]);
            float2 vbf = __bfloat1622float2(vb[j]);
            pa += qr[2 * j] * kaf.x + qr[2 * j + 1] * kaf.y;
            pb += qr[2 * j] * kbf.x + qr[2 * j + 1] * kbf.y;
            va_f[2 * j] = vaf.x; va_f[2 * j + 1] = vaf.y;
            vb_f[2 * j] = vbf.x; vb_f[2 * j + 1] = vbf.y;
        }
#pragma unroll
        for (int d = 1; d < 8; d <<= 1) {
            pa += __shfl_xor_sync(0xffffffffu, pa, d);
            pb += __shfl_xor_sync(0xffffffffu, pb, d);
        }
        float ea = __expf(pa * coef);
        float eb = __expf(pb * coef);
        l += ea + eb;
#pragma unroll
        for (int j = 0; j < 6; j++)
            acc[j] += ea * va_f[j] + eb * vb_f[j];
    }
    if (e < s1) {
        int sn = src[e];
        const __nv_bfloat162* kp = (const __nv_bfloat162*)(g_kb + (size_t)sn * DD + off);
        const __nv_bfloat162* vp = (const __nv_bfloat162*)(g_vb + (size_t)sn * DD + off);
        float vv[6];
        float p = 0.f;
#pragma unroll
        for (int j = 0; j < 3; j++) {
            float2 kf = __bfloat1622float2(kp[j]);
            float2 vf = __bfloat1622float2(vp[j]);
            p += qr[2 * j] * kf.x + qr[2 * j + 1] * kf.y;
            vv[2 * j] = vf.x; vv[2 * j + 1] = vf.y;
        }
#pragma unroll
        for (int d = 1; d < 8; d <<= 1) p += __shfl_xor_sync(0xffffffffu, p, d);
        float es = __expf(p * coef);
        l += es;
#pragma unroll
        for (int j = 0; j < 6; j++) acc[j] += es * vv[j];
    }
    float invl = (s1 > s0) ? (1.f / l) : 0.f;
    __nv_bfloat162* op = (__nv_bfloat162*)(g_aggb + (size_t)warp * DD + off);
#pragma unroll
    for (int j = 0; j < 3; j++)
        op[j] = __floats2bfloat162_rn(acc[2 * j] * invl, acc[2 * j + 1] * invl);
}

// ---------------- bf16 tensor-core GEMM: m16n8k16, cp.async double buffer ----------------
// A: bf16 [M][K] row-major. Bt: bf16 [N][K] (pre-transposed weights).
// Grid: x = N tile, y = M tile.
#define BM 128
#define BN 64
#define BK 32
#define AKS 40   // 32 + 8 pad (bf16 elems); 20-word row stride -> conflict-free
#define BKS 40

__device__ __forceinline__ void mma_bf16(float& c0, float& c1, float& c2, float& c3,
                                         unsigned a0, unsigned a1, unsigned a2, unsigned a3,
                                         unsigned b0, unsigned b1) {
    asm volatile(
        "mma.sync.aligned.m16n8k16.row.col.f32.bf16.bf16.f32 "
        "{%0,%1,%2,%3}, {%4,%5,%6,%7}, {%8,%9}, {%0,%1,%2,%3};"
        : "+f"(c0), "+f"(c1), "+f"(c2), "+f"(c3)
        : "r"(a0), "r"(a1), "r"(a2), "r"(a3), "r"(b0), "r"(b1));
}

// mode: 0 proj fp32, 1 gelu->bf16 mlp1, 2 residual->out fp32, 3 qkv scatter
__global__ void __launch_bounds__(256) gemm_kernel(
        const bf16* __restrict__ A, const bf16* __restrict__ Bt,
        const float* __restrict__ bias, float* __restrict__ out,
        const float* __restrict__ res, int M, int K, int Nc, int mode) {
    __shared__ bf16 As[2][BM][AKS];
    __shared__ bf16 Bs[2][BN][BKS];
    int tid = threadIdx.x;
    int lane = tid & 31;
    int wid = tid >> 5;
    int warp_m = wid & 3;
    int warp_n = wid >> 2;
    int m0 = blockIdx.y * BM;
    int n0 = blockIdx.x * BN;
    int gid = lane >> 2;
    int tig = lane & 3;

    int cp_row = tid >> 2;          // 0..63
    int cp_c = (tid & 3) * 8;       // bf16 elems, 16B chunks

    float acc[2][4][4];
#pragma unroll
    for (int mt = 0; mt < 2; mt++)
#pragma unroll
        for (int nt = 0; nt < 4; nt++)
#pragma unroll
            for (int j = 0; j < 4; j++) acc[mt][nt][j] = 0.f;

    int niter = K / BK;

#define LOAD_STAGE(it, buf)                                                            \
    {                                                                                  \
        int k0s = (it) * BK;                                                           \
        _Pragma("unroll")                                                              \
        for (int i = 0; i < 2; i++) {                                                  \
            int row = cp_row + i * 64;                                                 \
            const bf16* srcp = A + (size_t)(m0 + row) * K + k0s + cp_c;                \
            unsigned dstp = (unsigned)__cvta_generic_to_shared(&As[buf][row][cp_c]);   \
            int sz = (m0 + row < M) ? 16 : 0;                                          \
            asm volatile("cp.async.cg.shared.global [%0], [%1], 16, %2;\n"             \
                         :: "r"(dstp), "l"(srcp), "r"(sz));                            \
        }                                                                              \
        {                                                                              \
            const bf16* srcp = Bt + (size_t)(n0 + cp_row) * K + k0s + cp_c;            \
            unsigned dstp = (unsigned)__cvta_generic_to_shared(&Bs[buf][cp_row][cp_c]); \
            asm volatile("cp.async.cg.shared.global [%0], [%1], 16;\n"                 \
                         :: "r"(dstp), "l"(srcp));                                     \
        }                                                                              \
        asm volatile("cp.async.commit_group;\n");                                      \
    }

    LOAD_STAGE(0, 0);

    for (int it = 0; it < niter; it++) {
        int buf = it & 1;
        asm volatile("cp.async.wait_group 0;\n" ::: "memory");
        __syncthreads();
        if (it + 1 < niter) LOAD_STAGE(it + 1, buf ^ 1);

#pragma unroll
        for (int kk = 0; kk < 2; kk++) {       // two k16 chunks per BK=32
            int w0 = kk * 8 + tig;             // 32-bit word index within row
            unsigned a[2][4];
#pragma unroll
            for (int mt = 0; mt < 2; mt++) {
                int r = warp_m * 32 + mt * 16 + gid;
                const unsigned* r0 = (const unsigned*)&As[buf][r][0];
                const unsigned* r8 = (const unsigned*)&As[buf][r + 8][0];
                a[mt][0] = r0[w0];
                a[mt][1] = r8[w0];
                a[mt][2] = r0[w0 + 4];
                a[mt][3] = r8[w0 + 4];
            }
            unsigned b[4][2];
#pragma unroll
            for (int nt = 0; nt < 4; nt++) {
                int n = warp_n * 32 + nt * 8 + gid;
                const unsigned* rn = (const unsigned*)&Bs[buf][n][0];
                b[nt][0] = rn[w0];
                b[nt][1] = rn[w0 + 4];
            }
#pragma unroll
            for (int mt = 0; mt < 2; mt++)
#pragma unroll
                for (int nt = 0; nt < 4; nt++)
                    mma_bf16(acc[mt][nt][0], acc[mt][nt][1], acc[mt][nt][2], acc[mt][nt][3],
                             a[mt][0], a[mt][1], a[mt][2], a[mt][3],
                             b[nt][0], b[nt][1]);
        }
        __syncthreads();
    }

    // epilogue
#pragma unroll
    for (int mt = 0; mt < 2; mt++) {
#pragma unroll
        for (int nt = 0; nt < 4; nt++) {
#pragma unroll
            for (int half = 0; half < 2; half++) {
                int m = m0 + warp_m * 32 + mt * 16 + gid + half * 8;
                if (m >= M) continue;
#pragma unroll
                for (int j = 0; j < 2; j++) {
                    int n = n0 + warp_n * 32 + nt * 8 + 2 * tig + j;
                    float val = acc[mt][nt][half * 2 + j] + bias[n];
                    if (mode == 0) {
                        out[(size_t)m * Nc + n] = val;
                    } else if (mode == 1) {
                        g_mlp1b[(size_t)m * DFF + n] = __float2bfloat16_rn(val * normcdff(val));
                    } else if (mode == 2) {
                        out[(size_t)m * Nc + n] = val + res[(size_t)m * Nc + n];
                    } else {
                        int hh = n / 144;
                        int r = n - hh * 144;
                        int w = r / DHH;
                        int dd = r - w * DHH;
                        size_t o = (size_t)m * DD + hh * DHH + dd;
                        if (w == 0) g_q[o] = val;
                        else if (w == 1) g_kb[o] = __float2bfloat16_rn(val);
                        else g_vb[o] = __float2bfloat16_rn(val);
                    }
                }
            }
        }
    }
}

// ---------------- launch ----------------
static inline void* sym(const void* s) {
    void* p = nullptr;
    cudaGetSymbolAddress(&p, s);
    return p;
}

extern "C" void kernel_launch(void* const* d_in, const int* in_sizes, int n_in,
                              void* d_out, int out_size) {
    const float* x = (const float*)d_in[0];
    const void* mask = d_in[1];
    const int* src = (const int*)d_in[2];
    const int* dst = (const int*)d_in[3];
    const float* ln1_g = (const float*)d_in[4];
    const float* ln1_b = (const float*)d_in[5];
    const float* Wqkv = (const float*)d_in[6];
    const float* bqkv = (const float*)d_in[7];
    const float* Wout = (const float*)d_in[8];
    const float* bout = (const float*)d_in[9];
    const float* ln2_g = (const float*)d_in[10];
    const float* ln2_b = (const float*)d_in[11];
    const float* W1 = (const float*)d_in[12];
    const float* b1 = (const float*)d_in[13];
    const float* W2 = (const float*)d_in[14];
    const float* b2 = (const float*)d_in[15];
    float* out = (float*)d_out;

    bf16* hnb = (bf16*)sym(g_hnb);
    bf16* aggb = (bf16*)sym(g_aggb);
    float* proj = (float*)sym(g_proj);
    float* t1 = (float*)sym(g_t1);
    bf16* hn2b = (bf16*)sym(g_hn2b);
    bf16* mlp1b = (bf16*)sym(g_mlp1b);
    bf16* wqkvT = (bf16*)sym(g_wqkvT);
    bf16* woutT = (bf16*)sym(g_woutT);
    bf16* w1T = (bf16*)sym(g_w1T);
    bf16* w2T = (bf16*)sym(g_w2T);

    // 0. mask dtype detection + weight transposes (independent prep)
    init_flag_kernel<<<1, 1>>>();
    detect_mask_kernel<<<(NN / 4 + 255) / 256, 256>>>((const unsigned*)mask);
    wtrans_kernel<<<(DD * D3 + 255) / 256, 256>>>(Wqkv, wqkvT, DD, D3);
    wtrans_kernel<<<(DD * DD + 255) / 256, 256>>>(Wout, woutT, DD, DD);
    wtrans_kernel<<<(DD * DFF + 255) / 256, 256>>>(W1, w1T, DD, DFF);
    wtrans_kernel<<<(DFF * DD + 255) / 256, 256>>>(W2, w2T, DFF, DD);

    // 1. permutation
    blockscan_kernel<<<NB, 1024>>>(mask);
    scan_sums_kernel<<<1, 128>>>();
    ranks_kernel<<<(NN + 255) / 256, 256>>>(mask);

    // 2. LN1 fused with gather -> bf16
    ln_kernel<<<(NN + 7) / 8, 256>>>(x, ln1_g, ln1_b);

    // 3. CSR offsets
    rowstart_kernel<<<(EE + 255) / 256, 256>>>(dst);

    // 4. QKV GEMM (scatter epilogue)
    {
        dim3 grid(D3 / BN, (NN + BM - 1) / BM);
        gemm_kernel<<<grid, 256>>>(hnb, wqkvT, bqkv, nullptr, nullptr, NN, DD, D3, 3);
    }

    // 5. graph attention -> bf16 agg
    attn_kernel<<<(NN * 32 + 255) / 256, 256>>>(src);

    // 6. out-projection -> fp32 proj
    {
        dim3 grid(DD / BN, (NN + BM - 1) / BM);
        gemm_kernel<<<grid, 256>>>(aggb, woutT, bout, proj, nullptr, NN, DD, DD, 0);
    }

    // 7. fused residual + unpermute + LN2 (t1 fp32, hn2 bf16)
    resln_kernel<<<(NN + 7) / 8, 256>>>(x, ln2_g, ln2_b);

    // 8. MLP up + GELU -> bf16 mlp1
    {
        dim3 grid(DFF / BN, (NN + BM - 1) / BM);
        gemm_kernel<<<grid, 256>>>(hn2b, w1T, b1, nullptr, nullptr, NN, DD, DFF, 1);
    }

    // 9. MLP down + residual -> out fp32
    {
        dim3 grid(DD / BN, (NN + BM - 1) / BM);
        gemm_kernel<<<grid, 256>>>(mlp1b, w2T, b2, out, t1, NN, DFF, DD, 2);
    }
}